// round 2
// baseline (speedup 1.0000x reference)
#include <cuda_runtime.h>

#define V_N  100000
#define B_N  8
#define FC_N 200000
#define U_N  1024
#define T_N  110000
#define K_N  2
#define EPS_F 1e-5f

#define NSCAN_BLK ((V_N + 1023) / 1024)   // 98

// ---- scratch (static __device__, no allocs) ----
__device__ float4 g_fn[FC_N * B_N];       // face normals [f][b], 25.6 MB
__device__ float4 g_vn[V_N * B_N];        // vertex normals [v][b], 12.8 MB
__device__ int    g_off[V_N + 1];         // CSR offsets
__device__ int    g_cursor[V_N];          // scatter cursors / temp counts
__device__ int    g_csr[FC_N * 3];        // face ids per vertex slot
__device__ int    g_blocksums[NSCAN_BLK]; // scan partials

// ============ CSR build ============
__global__ __launch_bounds__(256) void k_zero_counts() {
    int v = blockIdx.x * blockDim.x + threadIdx.x;
    if (v < V_N) g_cursor[v] = 0;
}

__global__ __launch_bounds__(256) void k_count(const int* __restrict__ vi) {
    int i = blockIdx.x * blockDim.x + threadIdx.x;
    if (i < FC_N * 3) atomicAdd(&g_cursor[__ldg(&vi[i])], 1);
}

// block-level reduce of counts (1024 per block)
__global__ __launch_bounds__(1024) void k_scan1() {
    __shared__ int s[1024];
    int v = blockIdx.x * 1024 + threadIdx.x;
    s[threadIdx.x] = (v < V_N) ? g_cursor[v] : 0;
    __syncthreads();
    for (int st = 512; st > 0; st >>= 1) {
        if (threadIdx.x < st) s[threadIdx.x] += s[threadIdx.x + st];
        __syncthreads();
    }
    if (threadIdx.x == 0) g_blocksums[blockIdx.x] = s[0];
}

// exclusive scan of block sums (single block)
__global__ __launch_bounds__(128) void k_scan2() {
    __shared__ int s[128];
    int i = threadIdx.x;
    s[i] = (i < NSCAN_BLK) ? g_blocksums[i] : 0;
    __syncthreads();
    // Hillis-Steele inclusive
    for (int st = 1; st < 128; st <<= 1) {
        int val = (i >= st) ? s[i - st] : 0;
        __syncthreads();
        s[i] += val;
        __syncthreads();
    }
    if (i < NSCAN_BLK) g_blocksums[i] = (i == 0) ? 0 : s[i - 1];  // exclusive
    if (i == 0) g_off[V_N] = FC_N * 3;
}

// per-block exclusive scan of counts + block offset -> g_off / g_cursor
__global__ __launch_bounds__(1024) void k_scan3() {
    __shared__ int s[1024];
    int v = blockIdx.x * 1024 + threadIdx.x;
    int my = (v < V_N) ? g_cursor[v] : 0;
    s[threadIdx.x] = my;
    __syncthreads();
    for (int st = 1; st < 1024; st <<= 1) {
        int val = (threadIdx.x >= st) ? s[threadIdx.x - st] : 0;
        __syncthreads();
        s[threadIdx.x] += val;
        __syncthreads();
    }
    if (v < V_N) {
        int excl = s[threadIdx.x] - my + g_blocksums[blockIdx.x];
        g_off[v]    = excl;
        g_cursor[v] = excl;
    }
}

__global__ __launch_bounds__(256) void k_scatter(const int* __restrict__ vi) {
    int i = blockIdx.x * blockDim.x + threadIdx.x;
    if (i >= FC_N * 3) return;
    int v = __ldg(&vi[i]);
    int pos = atomicAdd(&g_cursor[v], 1);
    g_csr[pos] = i / 3;   // face id
}

// ============ face normals (no atomics) ============
__global__ __launch_bounds__(256) void k_face_normals(
    const float* __restrict__ verts, const int* __restrict__ vi)
{
    int tid = blockIdx.x * blockDim.x + threadIdx.x;
    if (tid >= FC_N * B_N) return;
    int f = tid >> 3;
    int b = tid & 7;

    int i0 = __ldg(&vi[f * 3 + 0]);
    int i1 = __ldg(&vi[f * 3 + 1]);
    int i2 = __ldg(&vi[f * 3 + 2]);

    const float* vb = verts + (size_t)b * (V_N * 3);
    float ax = __ldg(&vb[i0 * 3 + 0]), ay = __ldg(&vb[i0 * 3 + 1]), az = __ldg(&vb[i0 * 3 + 2]);
    float bx = __ldg(&vb[i1 * 3 + 0]), by = __ldg(&vb[i1 * 3 + 1]), bz = __ldg(&vb[i1 * 3 + 2]);
    float cx = __ldg(&vb[i2 * 3 + 0]), cy = __ldg(&vb[i2 * 3 + 1]), cz = __ldg(&vb[i2 * 3 + 2]);

    float e1x = bx - ax, e1y = by - ay, e1z = bz - az;
    float e2x = cx - ax, e2y = cy - ay, e2z = cz - az;
    float nx = e1y * e2z - e1z * e2y;
    float ny = e1z * e2x - e1x * e2z;
    float nz = e1x * e2y - e1y * e2x;

    float nrm = sqrtf(nx * nx + ny * ny + nz * nz);
    if (nrm >= EPS_F) {
        float inv = 1.f / nrm;
        nx *= inv; ny *= inv; nz *= inv;
    }
    g_fn[tid] = make_float4(nx, ny, nz, 0.f);
}

// ============ gather + normalize (fused) ============
__global__ __launch_bounds__(256) void k_gather_norm() {
    int tid = blockIdx.x * blockDim.x + threadIdx.x;
    if (tid >= V_N * B_N) return;
    int v = tid >> 3;
    int b = tid & 7;

    int s = __ldg(&g_off[v]);
    int e = __ldg(&g_off[v + 1]);

    float ax = 0.f, ay = 0.f, az = 0.f;
    for (int j = s; j < e; j++) {
        int f = __ldg(&g_csr[j]);                 // broadcast across 8 lanes
        float4 n = g_fn[f * B_N + b];             // coalesced 128B per 8 lanes
        ax += n.x; ay += n.y; az += n.z;
    }
    float nrm = sqrtf(ax * ax + ay * ay + az * az);
    if (nrm >= EPS_F) {
        float inv = 1.f / nrm;
        ax *= inv; ay *= inv; az *= inv;
    }
    g_vn[tid] = make_float4(ax, ay, az, 0.f);
}

// ============ sample pass (predicated) ============
__global__ __launch_bounds__(256) void sample_pass_kernel(
    const float* __restrict__ bary,
    const float* __restrict__ vt,
    const int*   __restrict__ idximg,
    const int*   __restrict__ v2uv,
    float*       __restrict__ out)
{
    __shared__ float s[32 * B_N * 3];

    int local = threadIdx.x;
    int vloc  = local >> 3;
    int b     = local & 7;
    int v     = blockIdx.x * 32 + vloc;

    float accx = 0.f, accy = 0.f, accz = 0.f;

    if (v < V_N) {
        #pragma unroll
        for (int k = 0; k < K_N; k++) {
            int t = __ldg(&v2uv[v * K_N + k]);
            float u  = __ldg(&vt[t * 2 + 0]);
            float wv = __ldg(&vt[t * 2 + 1]);

            float ix = u  * (float)U_N - 0.5f;
            float iy = wv * (float)U_N - 0.5f;
            float x0f = floorf(ix), y0f = floorf(iy);
            int x0 = (int)x0f, y0 = (int)y0f;
            float wx1 = ix - x0f, wx0 = 1.f - wx1;
            float wy1 = iy - y0f, wy0 = 1.f - wy1;

            #pragma unroll
            for (int tap = 0; tap < 4; tap++) {
                int xi = x0 + (tap & 1);
                int yi = y0 + (tap >> 1);
                bool inb = (xi >= 0) & (xi < U_N) & (yi >= 0) & (yi < U_N);
                int xc = min(max(xi, 0), U_N - 1);
                int yc = min(max(yi, 0), U_N - 1);
                int pix = yc * U_N + xc;

                int j0 = __ldg(&idximg[pix * 3 + 0]);
                int j1 = __ldg(&idximg[pix * 3 + 1]);
                int j2 = __ldg(&idximg[pix * 3 + 2]);
                bool valid = inb & (j0 != -1) & (j1 != -1) & (j2 != -1);

                float wt = ((tap & 1) ? wx1 : wx0) * ((tap >> 1) ? wy1 : wy0);
                wt = valid ? wt : 0.f;

                j0 = min(max(j0, 0), V_N - 1);
                j1 = min(max(j1, 0), V_N - 1);
                j2 = min(max(j2, 0), V_N - 1);

                float b0 = __ldg(&bary[pix * 3 + 0]);
                float b1 = __ldg(&bary[pix * 3 + 1]);
                float b2 = __ldg(&bary[pix * 3 + 2]);

                float4 n0 = g_vn[j0 * B_N + b];
                float4 n1 = g_vn[j1 * B_N + b];
                float4 n2 = g_vn[j2 * B_N + b];

                accx += wt * (b0 * n0.x + b1 * n1.x + b2 * n2.x);
                accy += wt * (b0 * n0.y + b1 * n1.y + b2 * n2.y);
                accz += wt * (b0 * n0.z + b1 * n1.z + b2 * n2.z);
            }
        }
    }

    float sc = 1.f / (float)K_N;
    s[b * 96 + vloc * 3 + 0] = accx * sc;
    s[b * 96 + vloc * 3 + 1] = accy * sc;
    s[b * 96 + vloc * 3 + 2] = accz * sc;
    __syncthreads();

    int v0 = blockIdx.x * 32;
    for (int i = local; i < 32 * B_N * 3; i += 256) {
        int bb = i / 96;
        int r  = i - bb * 96;
        int vv = v0 + r / 3;
        if (vv < V_N) out[(size_t)bb * (V_N * 3) + (size_t)v0 * 3 + r] = s[i];
    }
}

extern "C" void kernel_launch(void* const* d_in, const int* in_sizes, int n_in,
                              void* d_out, int out_size)
{
    const float* verts  = (const float*)d_in[0];
    const float* bary   = (const float*)d_in[1];
    const float* vt     = (const float*)d_in[2];
    const int*   vi     = (const int*)  d_in[3];
    const int*   idximg = (const int*)  d_in[4];
    const int*   v2uv   = (const int*)  d_in[5];
    float*       out    = (float*)d_out;

    (void)in_sizes; (void)n_in; (void)out_size;

    // CSR build
    k_zero_counts<<<(V_N + 255) / 256, 256>>>();
    k_count<<<(FC_N * 3 + 255) / 256, 256>>>(vi);
    k_scan1<<<NSCAN_BLK, 1024>>>();
    k_scan2<<<1, 128>>>();
    k_scan3<<<NSCAN_BLK, 1024>>>();
    k_scatter<<<(FC_N * 3 + 255) / 256, 256>>>(vi);

    // normals
    k_face_normals<<<(FC_N * B_N + 255) / 256, 256>>>(verts, vi);
    k_gather_norm<<<(V_N * B_N + 255) / 256, 256>>>();

    // sampling
    sample_pass_kernel<<<(V_N + 31) / 32, 256>>>(bary, vt, idximg, v2uv, out);
}

// round 3
// speedup vs baseline: 1.3603x; 1.3603x over previous
#include <cuda_runtime.h>

#define V_N  100000
#define B_N  8
#define FC_N 200000
#define U_N  1024
#define T_N  110000
#define K_N  2
#define EPS_F 1e-5f

// Scratch vertex normals, layout [V][B] of float4 (16B aligned), 12.8 MB.
__device__ float4 g_vn[V_N * B_N];

__device__ __forceinline__ void red_add_v4(float4* ptr, float x, float y, float z) {
    asm volatile("red.global.add.v4.f32 [%0], {%1, %2, %3, %4};"
                 :: "l"(ptr), "f"(x), "f"(y), "f"(z), "f"(0.0f)
                 : "memory");
}

__global__ __launch_bounds__(256) void zero_vn_kernel() {
    int i = blockIdx.x * blockDim.x + threadIdx.x;
    if (i < V_N * B_N) g_vn[i] = make_float4(0.f, 0.f, 0.f, 0.f);
}

// One thread per (face, batch); b fastest so 8 lanes share vi[f].
// 3 vector reductions per thread instead of 9 scalar atomics.
__global__ __launch_bounds__(256) void face_pass_kernel(
    const float* __restrict__ verts, const int* __restrict__ vi)
{
    int tid = blockIdx.x * blockDim.x + threadIdx.x;
    if (tid >= FC_N * B_N) return;
    int f = tid >> 3;
    int b = tid & 7;

    int i0 = __ldg(&vi[f * 3 + 0]);
    int i1 = __ldg(&vi[f * 3 + 1]);
    int i2 = __ldg(&vi[f * 3 + 2]);

    const float* vb = verts + (size_t)b * (V_N * 3);
    float ax = __ldg(&vb[i0 * 3 + 0]), ay = __ldg(&vb[i0 * 3 + 1]), az = __ldg(&vb[i0 * 3 + 2]);
    float bx = __ldg(&vb[i1 * 3 + 0]), by = __ldg(&vb[i1 * 3 + 1]), bz = __ldg(&vb[i1 * 3 + 2]);
    float cx = __ldg(&vb[i2 * 3 + 0]), cy = __ldg(&vb[i2 * 3 + 1]), cz = __ldg(&vb[i2 * 3 + 2]);

    float e1x = bx - ax, e1y = by - ay, e1z = bz - az;
    float e2x = cx - ax, e2y = cy - ay, e2z = cz - az;
    float nx = e1y * e2z - e1z * e2y;
    float ny = e1z * e2x - e1x * e2z;
    float nz = e1x * e2y - e1y * e2x;

    float nrm = sqrtf(nx * nx + ny * ny + nz * nz);
    if (nrm >= EPS_F) {
        float inv = 1.f / nrm;
        nx *= inv; ny *= inv; nz *= inv;
    }

    red_add_v4(&g_vn[i0 * B_N + b], nx, ny, nz);
    red_add_v4(&g_vn[i1 * B_N + b], nx, ny, nz);
    red_add_v4(&g_vn[i2 * B_N + b], nx, ny, nz);
}

__global__ __launch_bounds__(256) void norm_vn_kernel() {
    int i = blockIdx.x * blockDim.x + threadIdx.x;
    if (i >= V_N * B_N) return;
    float4 v = g_vn[i];
    float nrm = sqrtf(v.x * v.x + v.y * v.y + v.z * v.z);
    if (nrm >= EPS_F) {
        float inv = 1.f / nrm;
        v.x *= inv; v.y *= inv; v.z *= inv;
    }
    v.w = 0.f;
    g_vn[i] = v;
}

// One thread per (vertex, batch); b fastest (8 lanes of a vertex share all
// pixel-data loads; vn gathers are 128B-contiguous per 8-lane group).
__global__ __launch_bounds__(256) void sample_pass_kernel(
    const float* __restrict__ bary,
    const float* __restrict__ vt,
    const int*   __restrict__ idximg,
    const int*   __restrict__ v2uv,
    float*       __restrict__ out)
{
    __shared__ float s[32 * B_N * 3];

    int local = threadIdx.x;
    int vloc  = local >> 3;
    int b     = local & 7;
    int v     = blockIdx.x * 32 + vloc;

    float accx = 0.f, accy = 0.f, accz = 0.f;

    if (v < V_N) {
        #pragma unroll
        for (int k = 0; k < K_N; k++) {
            int t = __ldg(&v2uv[v * K_N + k]);
            float u  = __ldg(&vt[t * 2 + 0]);
            float wv = __ldg(&vt[t * 2 + 1]);

            // ix = ((2u-1 + 1)*W - 1)*0.5 = u*W - 0.5
            float ix = u  * (float)U_N - 0.5f;
            float iy = wv * (float)U_N - 0.5f;
            float x0f = floorf(ix), y0f = floorf(iy);
            int x0 = (int)x0f, y0 = (int)y0f;
            float wx1 = ix - x0f, wx0 = 1.f - wx1;
            float wy1 = iy - y0f, wy0 = 1.f - wy1;

            #pragma unroll
            for (int tap = 0; tap < 4; tap++) {
                int xi = x0 + (tap & 1);
                int yi = y0 + (tap >> 1);
                bool inb = (xi >= 0) & (xi < U_N) & (yi >= 0) & (yi < U_N);
                int xc = min(max(xi, 0), U_N - 1);
                int yc = min(max(yi, 0), U_N - 1);
                int pix = yc * U_N + xc;

                int j0 = __ldg(&idximg[pix * 3 + 0]);
                int j1 = __ldg(&idximg[pix * 3 + 1]);
                int j2 = __ldg(&idximg[pix * 3 + 2]);
                bool valid = inb & (j0 != -1) & (j1 != -1) & (j2 != -1);

                float wt = ((tap & 1) ? wx1 : wx0) * ((tap >> 1) ? wy1 : wy0);
                wt = valid ? wt : 0.f;

                j0 = min(max(j0, 0), V_N - 1);
                j1 = min(max(j1, 0), V_N - 1);
                j2 = min(max(j2, 0), V_N - 1);

                float b0 = __ldg(&bary[pix * 3 + 0]);
                float b1 = __ldg(&bary[pix * 3 + 1]);
                float b2 = __ldg(&bary[pix * 3 + 2]);

                float4 n0 = __ldg(&g_vn[j0 * B_N + b]);
                float4 n1 = __ldg(&g_vn[j1 * B_N + b]);
                float4 n2 = __ldg(&g_vn[j2 * B_N + b]);

                accx += wt * (b0 * n0.x + b1 * n1.x + b2 * n2.x);
                accy += wt * (b0 * n0.y + b1 * n1.y + b2 * n2.y);
                accz += wt * (b0 * n0.z + b1 * n1.z + b2 * n2.z);
            }
        }
    }

    float sc = 1.f / (float)K_N;
    s[b * 96 + vloc * 3 + 0] = accx * sc;
    s[b * 96 + vloc * 3 + 1] = accy * sc;
    s[b * 96 + vloc * 3 + 2] = accz * sc;
    __syncthreads();

    // Coalesced write-out: out[b][v][c], 768 floats per block.
    int v0 = blockIdx.x * 32;
    for (int i = local; i < 32 * B_N * 3; i += 256) {
        int bb = i / 96;
        int r  = i - bb * 96;
        int vv = v0 + r / 3;
        if (vv < V_N) out[(size_t)bb * (V_N * 3) + (size_t)v0 * 3 + r] = s[i];
    }
}

extern "C" void kernel_launch(void* const* d_in, const int* in_sizes, int n_in,
                              void* d_out, int out_size)
{
    const float* verts  = (const float*)d_in[0];  // [B, V, 3]
    const float* bary   = (const float*)d_in[1];  // [U, U, 3]
    const float* vt     = (const float*)d_in[2];  // [T, 2]
    const int*   vi     = (const int*)  d_in[3];  // [Fc, 3]
    const int*   idximg = (const int*)  d_in[4];  // [U, U, 3]
    const int*   v2uv   = (const int*)  d_in[5];  // [V, K]
    float*       out    = (float*)d_out;          // [B, V, 3]

    (void)in_sizes; (void)n_in; (void)out_size;

    zero_vn_kernel<<<(V_N * B_N + 255) / 256, 256>>>();
    face_pass_kernel<<<(FC_N * B_N + 255) / 256, 256>>>(verts, vi);
    norm_vn_kernel<<<(V_N * B_N + 255) / 256, 256>>>();
    sample_pass_kernel<<<(V_N + 31) / 32, 256>>>(bary, vt, idximg, v2uv, out);
}

// round 4
// speedup vs baseline: 1.9833x; 1.4580x over previous
#include <cuda_runtime.h>
#include <cuda_fp16.h>

#define V_N  100000
#define B_N  8
#define FC_N 200000
#define U_N  1024
#define T_N  110000
#define K_N  2
#define EPS_F 1e-5f

// Scratch:
__device__ float4 g_vt[V_N * B_N];   // transposed verts [v][b] = (x,y,z,0), 12.8 MB
__device__ float4 g_vn[V_N * B_N];   // accumulated vertex normals [v][b], 12.8 MB
__device__ uint2  g_vnh[V_N * B_N];  // normalized vn as half4 [v][b], 6.4 MB

__device__ __forceinline__ void red_add_v4(float4* ptr, float x, float y, float z) {
    asm volatile("red.global.add.v4.f32 [%0], {%1, %2, %3, %4};"
                 :: "l"(ptr), "f"(x), "f"(y), "f"(z), "f"(0.0f)
                 : "memory");
}

// Transpose verts -> g_vt[v*8+b] AND zero g_vn. b fastest => coalesced writes.
__global__ __launch_bounds__(256) void prep_kernel(const float* __restrict__ verts) {
    int i = blockIdx.x * blockDim.x + threadIdx.x;
    if (i >= V_N * B_N) return;
    int v = i >> 3;
    int b = i & 7;
    const float* p = verts + (size_t)b * (V_N * 3) + v * 3;
    float x = __ldg(p), y = __ldg(p + 1), z = __ldg(p + 2);
    g_vt[i] = make_float4(x, y, z, 0.f);
    g_vn[i] = make_float4(0.f, 0.f, 0.f, 0.f);
}

// One thread per (face, batch); b fastest. Vertex loads are coalesced
// 128B per 8-lane group from g_vt; 3 vector reductions per thread.
__global__ __launch_bounds__(256) void face_pass_kernel(const int* __restrict__ vi)
{
    int tid = blockIdx.x * blockDim.x + threadIdx.x;
    if (tid >= FC_N * B_N) return;
    int f = tid >> 3;
    int b = tid & 7;

    int i0 = __ldg(&vi[f * 3 + 0]);
    int i1 = __ldg(&vi[f * 3 + 1]);
    int i2 = __ldg(&vi[f * 3 + 2]);

    float4 A = __ldg(&g_vt[i0 * B_N + b]);
    float4 Bv = __ldg(&g_vt[i1 * B_N + b]);
    float4 C = __ldg(&g_vt[i2 * B_N + b]);

    float e1x = Bv.x - A.x, e1y = Bv.y - A.y, e1z = Bv.z - A.z;
    float e2x = C.x - A.x,  e2y = C.y - A.y,  e2z = C.z - A.z;
    float nx = e1y * e2z - e1z * e2y;
    float ny = e1z * e2x - e1x * e2z;
    float nz = e1x * e2y - e1y * e2x;

    float nrm = sqrtf(nx * nx + ny * ny + nz * nz);
    if (nrm >= EPS_F) {
        float inv = 1.f / nrm;
        nx *= inv; ny *= inv; nz *= inv;
    }

    red_add_v4(&g_vn[i0 * B_N + b], nx, ny, nz);
    red_add_v4(&g_vn[i1 * B_N + b], nx, ny, nz);
    red_add_v4(&g_vn[i2 * B_N + b], nx, ny, nz);
}

// Normalize in fp32, emit half4 (values in [-1,1] -> safe precision).
__global__ __launch_bounds__(256) void norm_vn_kernel() {
    int i = blockIdx.x * blockDim.x + threadIdx.x;
    if (i >= V_N * B_N) return;
    float4 v = g_vn[i];
    float nrm = sqrtf(v.x * v.x + v.y * v.y + v.z * v.z);
    if (nrm >= EPS_F) {
        float inv = 1.f / nrm;
        v.x *= inv; v.y *= inv; v.z *= inv;
    }
    __half2 xy = __floats2half2_rn(v.x, v.y);
    __half2 z0 = __floats2half2_rn(v.z, 0.f);
    uint2 u;
    *reinterpret_cast<__half2*>(&u.x) = xy;
    *reinterpret_cast<__half2*>(&u.y) = z0;
    g_vnh[i] = u;
}

// One thread per (vertex, batch); b fastest. vn gathers are 64B/8-lane group.
__global__ __launch_bounds__(256) void sample_pass_kernel(
    const float* __restrict__ bary,
    const float* __restrict__ vt,
    const int*   __restrict__ idximg,
    const int*   __restrict__ v2uv,
    float*       __restrict__ out)
{
    __shared__ float s[32 * B_N * 3];

    int local = threadIdx.x;
    int vloc  = local >> 3;
    int b     = local & 7;
    int v     = blockIdx.x * 32 + vloc;

    float accx = 0.f, accy = 0.f, accz = 0.f;

    if (v < V_N) {
        #pragma unroll
        for (int k = 0; k < K_N; k++) {
            int t = __ldg(&v2uv[v * K_N + k]);
            float u  = __ldg(&vt[t * 2 + 0]);
            float wv = __ldg(&vt[t * 2 + 1]);

            float ix = u  * (float)U_N - 0.5f;
            float iy = wv * (float)U_N - 0.5f;
            float x0f = floorf(ix), y0f = floorf(iy);
            int x0 = (int)x0f, y0 = (int)y0f;
            float wx1 = ix - x0f, wx0 = 1.f - wx1;
            float wy1 = iy - y0f, wy0 = 1.f - wy1;

            #pragma unroll
            for (int tap = 0; tap < 4; tap++) {
                int xi = x0 + (tap & 1);
                int yi = y0 + (tap >> 1);
                bool inb = (xi >= 0) & (xi < U_N) & (yi >= 0) & (yi < U_N);
                int xc = min(max(xi, 0), U_N - 1);
                int yc = min(max(yi, 0), U_N - 1);
                int pix = yc * U_N + xc;

                int j0 = __ldg(&idximg[pix * 3 + 0]);
                int j1 = __ldg(&idximg[pix * 3 + 1]);
                int j2 = __ldg(&idximg[pix * 3 + 2]);
                bool valid = inb & (j0 != -1) & (j1 != -1) & (j2 != -1);

                float wt = ((tap & 1) ? wx1 : wx0) * ((tap >> 1) ? wy1 : wy0);
                wt = valid ? wt : 0.f;

                j0 = min(max(j0, 0), V_N - 1);
                j1 = min(max(j1, 0), V_N - 1);
                j2 = min(max(j2, 0), V_N - 1);

                float b0 = __ldg(&bary[pix * 3 + 0]);
                float b1 = __ldg(&bary[pix * 3 + 1]);
                float b2 = __ldg(&bary[pix * 3 + 2]);

                uint2 h0 = __ldg(&g_vnh[j0 * B_N + b]);
                uint2 h1 = __ldg(&g_vnh[j1 * B_N + b]);
                uint2 h2 = __ldg(&g_vnh[j2 * B_N + b]);

                float2 n0xy = __half22float2(*reinterpret_cast<__half2*>(&h0.x));
                float  n0z  = __low2float(*reinterpret_cast<__half2*>(&h0.y));
                float2 n1xy = __half22float2(*reinterpret_cast<__half2*>(&h1.x));
                float  n1z  = __low2float(*reinterpret_cast<__half2*>(&h1.y));
                float2 n2xy = __half22float2(*reinterpret_cast<__half2*>(&h2.x));
                float  n2z  = __low2float(*reinterpret_cast<__half2*>(&h2.y));

                accx += wt * (b0 * n0xy.x + b1 * n1xy.x + b2 * n2xy.x);
                accy += wt * (b0 * n0xy.y + b1 * n1xy.y + b2 * n2xy.y);
                accz += wt * (b0 * n0z    + b1 * n1z    + b2 * n2z);
            }
        }
    }

    float sc = 1.f / (float)K_N;
    s[b * 96 + vloc * 3 + 0] = accx * sc;
    s[b * 96 + vloc * 3 + 1] = accy * sc;
    s[b * 96 + vloc * 3 + 2] = accz * sc;
    __syncthreads();

    int v0 = blockIdx.x * 32;
    for (int i = local; i < 32 * B_N * 3; i += 256) {
        int bb = i / 96;
        int r  = i - bb * 96;
        int vv = v0 + r / 3;
        if (vv < V_N) out[(size_t)bb * (V_N * 3) + (size_t)v0 * 3 + r] = s[i];
    }
}

extern "C" void kernel_launch(void* const* d_in, const int* in_sizes, int n_in,
                              void* d_out, int out_size)
{
    const float* verts  = (const float*)d_in[0];  // [B, V, 3]
    const float* bary   = (const float*)d_in[1];  // [U, U, 3]
    const float* vt     = (const float*)d_in[2];  // [T, 2]
    const int*   vi     = (const int*)  d_in[3];  // [Fc, 3]
    const int*   idximg = (const int*)  d_in[4];  // [U, U, 3]
    const int*   v2uv   = (const int*)  d_in[5];  // [V, K]
    float*       out    = (float*)d_out;          // [B, V, 3]

    (void)in_sizes; (void)n_in; (void)out_size;

    prep_kernel<<<(V_N * B_N + 255) / 256, 256>>>(verts);
    face_pass_kernel<<<(FC_N * B_N + 255) / 256, 256>>>(vi);
    norm_vn_kernel<<<(V_N * B_N + 255) / 256, 256>>>();
    sample_pass_kernel<<<(V_N + 31) / 32, 256>>>(bary, vt, idximg, v2uv, out);
}

// round 5
// speedup vs baseline: 1.9988x; 1.0078x over previous
#include <cuda_runtime.h>
#include <cuda_fp16.h>

#define V_N  100000
#define B_N  8
#define FC_N 200000
#define U_N  1024
#define T_N  110000
#define K_N  2
#define EPS_F 1e-5f

// Scratch:
__device__ float4 g_vt[V_N * B_N];   // transposed verts [v][b] = (x,y,z,0), 12.8 MB
__device__ float4 g_vn[V_N * B_N];   // accumulated vertex normals [v][b], 12.8 MB
__device__ uint2  g_vnh[V_N * B_N];  // normalized vn as half4 [v][b], 6.4 MB

__device__ __forceinline__ void red_add_v4(float4* ptr, float x, float y, float z) {
    asm volatile("red.global.add.v4.f32 [%0], {%1, %2, %3, %4};"
                 :: "l"(ptr), "f"(x), "f"(y), "f"(z), "f"(0.0f)
                 : "memory");
}

// Transpose verts -> g_vt[v*8+b] AND zero g_vn. b fastest => coalesced writes.
__global__ __launch_bounds__(256) void prep_kernel(const float* __restrict__ verts) {
    int i = blockIdx.x * blockDim.x + threadIdx.x;
    if (i >= V_N * B_N) return;
    int v = i >> 3;
    int b = i & 7;
    const float* p = verts + (size_t)b * (V_N * 3) + v * 3;
    float x = __ldg(p), y = __ldg(p + 1), z = __ldg(p + 2);
    g_vt[i] = make_float4(x, y, z, 0.f);
    g_vn[i] = make_float4(0.f, 0.f, 0.f, 0.f);
}

// One thread per (face, batch); b fastest. Coalesced 128B/8-lane vertex loads,
// 3 vector reductions per thread.
__global__ __launch_bounds__(256) void face_pass_kernel(const int* __restrict__ vi)
{
    int tid = blockIdx.x * blockDim.x + threadIdx.x;
    if (tid >= FC_N * B_N) return;
    int f = tid >> 3;
    int b = tid & 7;

    int i0 = __ldg(&vi[f * 3 + 0]);
    int i1 = __ldg(&vi[f * 3 + 1]);
    int i2 = __ldg(&vi[f * 3 + 2]);

    float4 A  = __ldg(&g_vt[i0 * B_N + b]);
    float4 Bv = __ldg(&g_vt[i1 * B_N + b]);
    float4 C  = __ldg(&g_vt[i2 * B_N + b]);

    float e1x = Bv.x - A.x, e1y = Bv.y - A.y, e1z = Bv.z - A.z;
    float e2x = C.x - A.x,  e2y = C.y - A.y,  e2z = C.z - A.z;
    float nx = e1y * e2z - e1z * e2y;
    float ny = e1z * e2x - e1x * e2z;
    float nz = e1x * e2y - e1y * e2x;

    float nrm = sqrtf(nx * nx + ny * ny + nz * nz);
    if (nrm >= EPS_F) {
        float inv = 1.f / nrm;
        nx *= inv; ny *= inv; nz *= inv;
    }

    red_add_v4(&g_vn[i0 * B_N + b], nx, ny, nz);
    red_add_v4(&g_vn[i1 * B_N + b], nx, ny, nz);
    red_add_v4(&g_vn[i2 * B_N + b], nx, ny, nz);
}

// Normalize in fp32, emit half4.
__global__ __launch_bounds__(256) void norm_vn_kernel() {
    int i = blockIdx.x * blockDim.x + threadIdx.x;
    if (i >= V_N * B_N) return;
    float4 v = g_vn[i];
    float nrm = sqrtf(v.x * v.x + v.y * v.y + v.z * v.z);
    if (nrm >= EPS_F) {
        float inv = 1.f / nrm;
        v.x *= inv; v.y *= inv; v.z *= inv;
    }
    __half2 xy = __floats2half2_rn(v.x, v.y);
    __half2 z0 = __floats2half2_rn(v.z, 0.f);
    uint2 u;
    *reinterpret_cast<__half2*>(&u.x) = xy;
    *reinterpret_cast<__half2*>(&u.y) = z0;
    g_vnh[i] = u;
}

// Two-stage sample pass. Block = 32 vertices.
// Stage 1: 256 threads = (vloc, k, tap) tap-tasks: pixel math ONCE per tap,
//          results to smem (j's + premultiplied weights).
// Stage 2: 256 threads = (vloc, b): 8 smem tap entries, coalesced 64B/8-lane
//          vnh gathers, fp32 accumulate.
__global__ __launch_bounds__(256) void sample_pass_kernel(
    const float* __restrict__ bary,
    const float* __restrict__ vt,
    const int*   __restrict__ idximg,
    const int*   __restrict__ v2uv,
    float*       __restrict__ out)
{
    __shared__ int   sj0[256], sj1[256], sj2[256];
    __shared__ float sw0[256], sw1[256], sw2[256];
    __shared__ float sout[32 * B_N * 3];

    int local = threadIdx.x;

    // ---- stage 1: tap-task = (vloc, k, tap) ----
    {
        int vloc = local >> 3;
        int k    = (local >> 2) & 1;
        int tap  = local & 3;
        int v    = blockIdx.x * 32 + vloc;

        int j0 = -1, j1 = 0, j2 = 0;
        float w0 = 0.f, w1 = 0.f, w2 = 0.f;

        if (v < V_N) {
            int t = __ldg(&v2uv[v * K_N + k]);
            float u  = __ldg(&vt[t * 2 + 0]);
            float wv = __ldg(&vt[t * 2 + 1]);

            // ix = ((2u-1 + 1)*W - 1)*0.5 = u*W - 0.5
            float ix = u  * (float)U_N - 0.5f;
            float iy = wv * (float)U_N - 0.5f;
            float x0f = floorf(ix), y0f = floorf(iy);
            int x0 = (int)x0f, y0 = (int)y0f;
            float wx1 = ix - x0f, wx0 = 1.f - wx1;
            float wy1 = iy - y0f, wy0 = 1.f - wy1;

            int xi = x0 + (tap & 1);
            int yi = y0 + (tap >> 1);
            bool inb = (xi >= 0) & (xi < U_N) & (yi >= 0) & (yi < U_N);
            int xc = min(max(xi, 0), U_N - 1);
            int yc = min(max(yi, 0), U_N - 1);
            int pix = yc * U_N + xc;

            int a0 = __ldg(&idximg[pix * 3 + 0]);
            int a1 = __ldg(&idximg[pix * 3 + 1]);
            int a2 = __ldg(&idximg[pix * 3 + 2]);
            bool valid = inb & (a0 != -1) & (a1 != -1) & (a2 != -1);

            if (valid) {
                float wt = ((tap & 1) ? wx1 : wx0) * ((tap >> 1) ? wy1 : wy0);
                float b0 = __ldg(&bary[pix * 3 + 0]);
                float b1 = __ldg(&bary[pix * 3 + 1]);
                float b2 = __ldg(&bary[pix * 3 + 2]);
                j0 = min(max(a0, 0), V_N - 1);
                j1 = min(max(a1, 0), V_N - 1);
                j2 = min(max(a2, 0), V_N - 1);
                w0 = wt * b0; w1 = wt * b1; w2 = wt * b2;
            }
        }
        sj0[local] = j0; sj1[local] = j1; sj2[local] = j2;
        sw0[local] = w0; sw1[local] = w1; sw2[local] = w2;
    }
    __syncthreads();

    // ---- stage 2: (vloc, b) ----
    {
        int vloc = local >> 3;
        int b    = local & 7;

        float accx = 0.f, accy = 0.f, accz = 0.f;

        #pragma unroll
        for (int e = 0; e < 8; e++) {
            int idx = vloc * 8 + e;
            int j0 = sj0[idx];
            if (j0 < 0) continue;  // uniform across the 8-lane group
            int j1 = sj1[idx];
            int j2 = sj2[idx];
            float w0 = sw0[idx];
            float w1 = sw1[idx];
            float w2 = sw2[idx];

            uint2 h0 = __ldg(&g_vnh[j0 * B_N + b]);
            uint2 h1 = __ldg(&g_vnh[j1 * B_N + b]);
            uint2 h2 = __ldg(&g_vnh[j2 * B_N + b]);

            float2 n0xy = __half22float2(*reinterpret_cast<__half2*>(&h0.x));
            float  n0z  = __low2float(*reinterpret_cast<__half2*>(&h0.y));
            float2 n1xy = __half22float2(*reinterpret_cast<__half2*>(&h1.x));
            float  n1z  = __low2float(*reinterpret_cast<__half2*>(&h1.y));
            float2 n2xy = __half22float2(*reinterpret_cast<__half2*>(&h2.x));
            float  n2z  = __low2float(*reinterpret_cast<__half2*>(&h2.y));

            accx += w0 * n0xy.x + w1 * n1xy.x + w2 * n2xy.x;
            accy += w0 * n0xy.y + w1 * n1xy.y + w2 * n2xy.y;
            accz += w0 * n0z    + w1 * n1z    + w2 * n2z;
        }

        float sc = 1.f / (float)K_N;
        sout[b * 96 + vloc * 3 + 0] = accx * sc;
        sout[b * 96 + vloc * 3 + 1] = accy * sc;
        sout[b * 96 + vloc * 3 + 2] = accz * sc;
    }
    __syncthreads();

    // Coalesced write-out: out[b][v][c], 768 floats per block.
    int v0 = blockIdx.x * 32;
    for (int i = local; i < 32 * B_N * 3; i += 256) {
        int bb = i / 96;
        int r  = i - bb * 96;
        int vv = v0 + r / 3;
        if (vv < V_N) out[(size_t)bb * (V_N * 3) + (size_t)v0 * 3 + r] = sout[i];
    }
}

extern "C" void kernel_launch(void* const* d_in, const int* in_sizes, int n_in,
                              void* d_out, int out_size)
{
    const float* verts  = (const float*)d_in[0];  // [B, V, 3]
    const float* bary   = (const float*)d_in[1];  // [U, U, 3]
    const float* vt     = (const float*)d_in[2];  // [T, 2]
    const int*   vi     = (const int*)  d_in[3];  // [Fc, 3]
    const int*   idximg = (const int*)  d_in[4];  // [U, U, 3]
    const int*   v2uv   = (const int*)  d_in[5];  // [V, K]
    float*       out    = (float*)d_out;          // [B, V, 3]

    (void)in_sizes; (void)n_in; (void)out_size;

    prep_kernel<<<(V_N * B_N + 255) / 256, 256>>>(verts);
    face_pass_kernel<<<(FC_N * B_N + 255) / 256, 256>>>(vi);
    norm_vn_kernel<<<(V_N * B_N + 255) / 256, 256>>>();
    sample_pass_kernel<<<(V_N + 31) / 32, 256>>>(bary, vt, idximg, v2uv, out);
}